// round 10
// baseline (speedup 1.0000x reference)
#include <cuda_runtime.h>
#include <cuda_bf16.h>
#include <cstdint>

// Problem constants (this instance): N=1e6 atoms, D=128, H=64, E=4, M=20000.
#define D_DIM 128
#define H_DIM 64
#define BM 128
#define NT 512
#define E_MAX 8
#define PERM_CAP 1250000
#define HIST_BLOCKS 512
#define GRID_PERSIST 148

// dynamic SMEM layout (bytes)
#define ALO_OFF   32768
#define OFF_BHI   65536
#define OFF_BLO   81920
#define OFF_SORIG 98304      // 2 x 128 ints
#define OFF_B1ALL 99328
#define OFF_W2ALL 101376
#define OFF_ETAG  103424     // 2 ints
#define SMEM_TOTAL 103936

#define BWORDS 4096          // per-element W1 image: 4096 u32 (16KB)

__device__ int g_count[E_MAX];
__device__ int g_cursor[E_MAX];
__device__ int g_done;
__device__ int g_perm[PERM_CAP];
__device__ uint32_t g_Whi[E_MAX * BWORDS];
__device__ uint32_t g_Wlo[E_MAX * BWORDS];

// ---------------------------------------------------------------------------
__global__ void k_prep(float* __restrict__ out, const float* __restrict__ W1,
                       int E, int M, int total_slots) {
    int i = blockIdx.x * blockDim.x + threadIdx.x;
    int stride = gridDim.x * blockDim.x;
    for (int j = i; j < M; j += stride) out[j] = 0.0f;
    for (int j = i; j < total_slots; j += stride) g_perm[j] = -1;
    if (i < E_MAX) g_count[i] = 0;
    if (i == E_MAX) g_done = 0;

    for (int it = i; it < E * D_DIM * 16; it += stride) {
        int e = it >> 11;
        int k = (it >> 4) & 127;
        int n4 = it & 15;
        float4 v = *reinterpret_cast<const float4*>(
            W1 + (size_t)e * D_DIM * H_DIM + (size_t)k * H_DIM + n4 * 4);
        __nv_bfloat16 hx = __float2bfloat16(v.x), hy = __float2bfloat16(v.y);
        __nv_bfloat16 hz = __float2bfloat16(v.z), hw = __float2bfloat16(v.w);
        float rx = v.x - __bfloat162float(hx), ry = v.y - __bfloat162float(hy);
        float rz = v.z - __bfloat162float(hz), rw = v.w - __bfloat162float(hw);
        __nv_bfloat162 hi01 = __halves2bfloat162(hx, hy);
        __nv_bfloat162 hi23 = __halves2bfloat162(hz, hw);
        __nv_bfloat162 lo01 = __floats2bfloat162_rn(rx, ry);
        __nv_bfloat162 lo23 = __floats2bfloat162_rn(rz, rw);
        int w = e * BWORDS + k * 32 + (((n4 >> 1) ^ (k & 7)) << 2) + (n4 & 1) * 2;
        g_Whi[w]     = *reinterpret_cast<uint32_t*>(&hi01);
        g_Whi[w + 1] = *reinterpret_cast<uint32_t*>(&hi23);
        g_Wlo[w]     = *reinterpret_cast<uint32_t*>(&lo01);
        g_Wlo[w + 1] = *reinterpret_cast<uint32_t*>(&lo23);
    }
}

__global__ void k_histscan(const int* __restrict__ zidx, int n, int E) {
    __shared__ int sh[E_MAX];
    if (threadIdx.x < E_MAX) sh[threadIdx.x] = 0;
    __syncthreads();
    int i = blockIdx.x * blockDim.x + threadIdx.x;
    int stride = gridDim.x * blockDim.x;
    for (int j = i; j < n; j += stride) atomicAdd(&sh[zidx[j]], 1);
    __syncthreads();
    if (threadIdx.x < E) atomicAdd(&g_count[threadIdx.x], sh[threadIdx.x]);
    __threadfence();
    __syncthreads();
    if (threadIdx.x == 0) {
        int t = atomicAdd(&g_done, 1);
        if (t == gridDim.x - 1) {
            int off = 0;
            for (int e = 0; e < E; e++) {
                g_cursor[e] = off;
                off += ((g_count[e] + BM - 1) / BM) * BM;
            }
        }
    }
}

__global__ void k_scatter(const int* __restrict__ zidx, int n) {
    __shared__ int s_cnt[E_MAX];
    __shared__ int s_off[E_MAX];
    if (threadIdx.x < E_MAX) s_cnt[threadIdx.x] = 0;
    __syncthreads();
    int i = blockIdx.x * blockDim.x + threadIdx.x;
    int e = -1;
    if (i < n) { e = zidx[i]; atomicAdd(&s_cnt[e], 1); }
    __syncthreads();
    if (threadIdx.x < E_MAX && s_cnt[threadIdx.x] > 0)
        s_off[threadIdx.x] = atomicAdd(&g_cursor[threadIdx.x], s_cnt[threadIdx.x]);
    __syncthreads();
    if (threadIdx.x < E_MAX) s_cnt[threadIdx.x] = 0;
    __syncthreads();
    if (i < n) {
        int pos = s_off[e] + atomicAdd(&s_cnt[e], 1);
        g_perm[pos] = i;
    }
}

__device__ __forceinline__ float sspf(float v) {
    return __logf(fmaf(0.5f, __expf(v), 0.5f));
}
__device__ __forceinline__ void mma_bf16(float* c, const uint32_t* a,
                                         const uint32_t b0, const uint32_t b1) {
    asm volatile(
        "mma.sync.aligned.m16n8k16.row.col.f32.bf16.bf16.f32 "
        "{%0,%1,%2,%3}, {%4,%5,%6,%7}, {%8,%9}, {%0,%1,%2,%3};"
        : "+f"(c[0]), "+f"(c[1]), "+f"(c[2]), "+f"(c[3])
        : "r"(a[0]), "r"(a[1]), "r"(a[2]), "r"(a[3]), "r"(b0), "r"(b1));
}
__device__ __forceinline__ void ldsm_x4(uint32_t* r, uint32_t addr) {
    asm volatile("ldmatrix.sync.aligned.m8n8.x4.shared.b16 {%0,%1,%2,%3}, [%4];"
                 : "=r"(r[0]), "=r"(r[1]), "=r"(r[2]), "=r"(r[3]) : "r"(addr));
}
__device__ __forceinline__ void ldsm_x4t(uint32_t* r, uint32_t addr) {
    asm volatile("ldmatrix.sync.aligned.m8n8.x4.trans.shared.b16 {%0,%1,%2,%3}, [%4];"
                 : "=r"(r[0]), "=r"(r[1]), "=r"(r[2]), "=r"(r[3]) : "r"(addr));
}
__device__ __forceinline__ uint32_t smem_u32(const void* p) {
    return (uint32_t)__cvta_generic_to_shared(p);
}
__device__ __forceinline__ uint32_t cvt_bf16x2(float v1, float v0) {
    uint32_t r;
    asm("cvt.rn.bf16x2.f32 %0, %1, %2;" : "=r"(r) : "f"(v1), "f"(v0));
    return r;
}

__device__ __forceinline__ void store_a(char* smem, float4 v, int row, int lane) {
    uint32_t* AhiW = reinterpret_cast<uint32_t*>(smem);
    uint32_t* AloW = reinterpret_cast<uint32_t*>(smem + ALO_OFF);
    uint32_t xi0 = __float_as_uint(v.x), xi1 = __float_as_uint(v.y);
    uint32_t xi2 = __float_as_uint(v.z), xi3 = __float_as_uint(v.w);
    uint32_t h01 = __byte_perm(xi0, xi1, 0x7632);
    uint32_t h23 = __byte_perm(xi2, xi3, 0x7632);
    float l0 = v.x - __uint_as_float(xi0 & 0xffff0000u);
    float l1 = v.y - __uint_as_float(xi1 & 0xffff0000u);
    float l2 = v.z - __uint_as_float(xi2 & 0xffff0000u);
    float l3 = v.w - __uint_as_float(xi3 & 0xffff0000u);
    uint32_t l01 = cvt_bf16x2(l1, l0);
    uint32_t l23 = cvt_bf16x2(l3, l2);
    int w = row * 64 + ((((lane >> 1) ^ (row & 7)) << 2) + (lane & 1) * 2);
    *reinterpret_cast<uint2*>(&AhiW[w]) = make_uint2(h01, h23);
    *reinterpret_cast<uint2*>(&AloW[w]) = make_uint2(l01, l23);
}

__device__ __forceinline__ void stage_B(char* smem, int e, int tid) {
    const uint4* ghi = reinterpret_cast<const uint4*>(&g_Whi[e * BWORDS]);
    const uint4* glo = reinterpret_cast<const uint4*>(&g_Wlo[e * BWORDS]);
    uint4* shi = reinterpret_cast<uint4*>(smem + OFF_BHI);
    uint4* slo = reinterpret_cast<uint4*>(smem + OFF_BLO);
    shi[tid] = ghi[tid]; shi[NT + tid] = ghi[NT + tid];
    slo[tid] = glo[tid]; slo[NT + tid] = glo[NT + tid];
}

// ---------------------------------------------------------------------------
// persistent main kernel: per tile [gather->STS | barrier | MMA(split acc) |
// epilogue | barrier]; no long-lived prefetch registers (RF freed for ILP);
// accumulators split into two banks to break the 3-HMMA chain per kb-step.
// ---------------------------------------------------------------------------
__global__ __launch_bounds__(NT, 1)
void k_main(const float* __restrict__ x, const int* __restrict__ zidx,
            const int* __restrict__ idx_m,
            const float* __restrict__ W1, const float* __restrict__ b1,
            const float* __restrict__ W2, const float* __restrict__ b2,
            float* __restrict__ out, int ntiles) {
    extern __shared__ char smem[];
    int*   sOrig = reinterpret_cast<int*>(smem + OFF_SORIG);   // [2][128]
    float* b1all = reinterpret_cast<float*>(smem + OFF_B1ALL);
    float* w2all = reinterpret_cast<float*>(smem + OFF_W2ALL);
    int*   eTag  = reinterpret_cast<int*>(smem + OFF_ETAG);    // [2]

    int tid = threadIdx.x;
    int wid = tid >> 5;
    int lane = tid & 31;

    int q = (ntiles + gridDim.x - 1) / gridDim.x;
    int tstart = blockIdx.x * q;
    int tend = min(ntiles, tstart + q);
    if (tstart >= tend) return;
    int L = tend - tstart;

    if (tid < E_MAX * H_DIM) {
        b1all[tid] = b1[tid];
        w2all[tid] = W2[tid];
    }
    if (tid < BM) sOrig[tid] = g_perm[(size_t)tstart * BM + tid];
    if (tid == 0) {
        int o0 = g_perm[(size_t)tstart * BM];
        eTag[0] = (o0 >= 0) ? zidx[o0] : -1;
    }
    __syncthreads();

    int e_cur = eTag[0];
    if (e_cur < 0) e_cur = 0;
    stage_B(smem, e_cur, tid);
    // (B consumed only after the gather barrier below)

    // fragment-lane decomposition (16 warps: 4 wm x 4 wn, warp tile 32x16)
    int wm = wid & 3;
    int wn = wid >> 2;
    int g = lane >> 2;
    int tg = lane & 3;
    int lane7 = lane & 7;
    int sub = lane >> 3;
    int subm = sub & 1;
    int subh = sub >> 1;

    uint32_t aHiBase = smem_u32(smem);
    uint32_t aLoBase = aHiBase + ALO_OFF;
    uint32_t bHiBase = smem_u32(smem + OFF_BHI);
    uint32_t bLoBase = smem_u32(smem + OFF_BLO);

    int aRow0 = (wm * 32 + subm * 8 + lane7) * 64;
    int aRow1 = aRow0 + 16 * 64;
    int aXor = 4 * lane7;
    int a4h = 4 * subh;
    int bConst = (subm * 8 + lane7) * 32 + ((4 * (wn * 2 + subh)) ^ (4 * lane7));

    for (int l = 0; l < L; l++) {
        int s = l & 1;
        const int* so = sOrig + s * BM;

        // ---- 1. gather tile l: LDG (batched, MLP=8) -> convert -> STS ----
        {
            float4 v[8];
#pragma unroll
            for (int it = 0; it < 8; it++) {
                int o = so[it * 16 + wid];
                v[it] = make_float4(0.f, 0.f, 0.f, 0.f);
                if (o >= 0)
                    v[it] = *reinterpret_cast<const float4*>(
                        x + (size_t)o * D_DIM + lane * 4);
            }
#pragma unroll
            for (int it = 0; it < 8; it++)
                store_a(smem, v[it], it * 16 + wid, lane);
        }
        // prefetch perm(l+1) into one register (committed after epilogue)
        int o1 = -1;
        if (tid < BM && l + 1 < L)
            o1 = g_perm[(size_t)(tstart + l + 1) * BM + tid];

        __syncthreads();   // A (and B on first iter / element change) ready

        // ---- 2. MMA(l): split accumulators accP (hi*hi), accQ (cross) ----
        float accP[2][2][4], accQ[2][2][4];
#pragma unroll
        for (int t2 = 0; t2 < 2; t2++)
#pragma unroll
            for (int u = 0; u < 2; u++)
#pragma unroll
                for (int qq = 0; qq < 4; qq++) {
                    accP[t2][u][qq] = 0.0f;
                    accQ[t2][u][qq] = 0.0f;
                }

#pragma unroll
        for (int kb = 0; kb < 8; kb++) {
            int aOff = (8 * kb + a4h) ^ aXor;
            uint32_t ahi0[4], ahi1[4], alo0[4], alo1[4], bhi[4], blo[4];
            ldsm_x4(ahi0, aHiBase + (aRow0 + aOff) * 4);
            ldsm_x4(ahi1, aHiBase + (aRow1 + aOff) * 4);
            ldsm_x4(alo0, aLoBase + (aRow0 + aOff) * 4);
            ldsm_x4(alo1, aLoBase + (aRow1 + aOff) * 4);
            ldsm_x4t(bhi, bHiBase + (kb * 512 + bConst) * 4);
            ldsm_x4t(blo, bLoBase + (kb * 512 + bConst) * 4);
#pragma unroll
            for (int u = 0; u < 2; u++) {
                mma_bf16(accP[0][u], ahi0, bhi[2 * u], bhi[2 * u + 1]);
                mma_bf16(accP[1][u], ahi1, bhi[2 * u], bhi[2 * u + 1]);
                mma_bf16(accQ[0][u], ahi0, blo[2 * u], blo[2 * u + 1]);
                mma_bf16(accQ[1][u], ahi1, blo[2 * u], blo[2 * u + 1]);
                mma_bf16(accQ[0][u], alo0, bhi[2 * u], bhi[2 * u + 1]);
                mma_bf16(accQ[1][u], alo1, bhi[2 * u], bhi[2 * u + 1]);
            }
        }

        // ---- 3. epilogue(l) ----
        {
            const float* b1s = b1all + e_cur * H_DIM;
            const float* w2s = w2all + e_cur * H_DIM;
            float b2e = b2[e_cur];
#pragma unroll
            for (int t2 = 0; t2 < 2; t2++) {
                float p0 = 0.0f, p1 = 0.0f;
#pragma unroll
                for (int u = 0; u < 2; u++) {
                    int c0 = wn * 16 + u * 8 + 2 * tg;
                    float a0 = accP[t2][u][0] + accQ[t2][u][0];
                    float a1 = accP[t2][u][1] + accQ[t2][u][1];
                    float a2 = accP[t2][u][2] + accQ[t2][u][2];
                    float a3 = accP[t2][u][3] + accQ[t2][u][3];
                    p0 = fmaf(sspf(a0 + b1s[c0]),     w2s[c0],     p0);
                    p0 = fmaf(sspf(a1 + b1s[c0 + 1]), w2s[c0 + 1], p0);
                    p1 = fmaf(sspf(a2 + b1s[c0]),     w2s[c0],     p1);
                    p1 = fmaf(sspf(a3 + b1s[c0 + 1]), w2s[c0 + 1], p1);
                }
                p0 += __shfl_xor_sync(0xffffffffu, p0, 1);
                p0 += __shfl_xor_sync(0xffffffffu, p0, 2);
                p1 += __shfl_xor_sync(0xffffffffu, p1, 1);
                p1 += __shfl_xor_sync(0xffffffffu, p1, 2);
                if (tg == 0) {
                    int r0 = wm * 32 + t2 * 16 + g;
                    int o0 = so[r0];
                    int oo1 = so[r0 + 8];
                    float bias = (wn == 0) ? b2e : 0.0f;
                    if (o0 >= 0) atomicAdd(&out[idx_m[o0]], p0 + bias);
                    if (oo1 >= 0) atomicAdd(&out[idx_m[oo1]], p1 + bias);
                }
            }
        }

        // ---- 4. commit perm(l+1) + element tag ----
        if (tid < BM) sOrig[(s ^ 1) * BM + tid] = o1;
        if (tid == 0) eTag[s ^ 1] = (o1 >= 0) ? zidx[o1] : -1;

        __syncthreads();   // A consumed, sOrig/eTag committed

        // ---- 5. element change (rare): restage B ----
        if (l + 1 < L) {
            int e_next = eTag[s ^ 1];
            if (e_next >= 0 && e_next != e_cur) {
                stage_B(smem, e_next, tid);
                e_cur = e_next;
                // no barrier needed: B consumed only after next iteration's
                // post-gather barrier
            }
        }
    }
}

// ---------------------------------------------------------------------------
extern "C" void kernel_launch(void* const* d_in, const int* in_sizes, int n_in,
                              void* d_out, int out_size) {
    const float* x    = (const float*)d_in[0];
    const int*   zidx = (const int*)d_in[1];
    const int*   idxm = (const int*)d_in[2];
    const float* W1   = (const float*)d_in[3];
    const float* b1   = (const float*)d_in[4];
    const float* W2   = (const float*)d_in[5];
    const float* b2   = (const float*)d_in[6];
    float* out = (float*)d_out;

    int N = in_sizes[1];
    int E = in_sizes[6];
    int M = out_size;

    int ntiles = (N + BM - 1) / BM + E;
    int total_slots = ntiles * BM;
    if (total_slots > PERM_CAP) total_slots = PERM_CAP;

    static int smem_set = 0;
    if (!smem_set) {
        cudaFuncSetAttribute(k_main, cudaFuncAttributeMaxDynamicSharedMemorySize,
                             SMEM_TOTAL);
        smem_set = 1;
    }

    k_prep<<<256, 256>>>(out, W1, E, M, total_slots);
    k_histscan<<<HIST_BLOCKS, 256>>>(zidx, N, E);
    k_scatter<<<(N + 255) / 256, 256>>>(zidx, N);
    k_main<<<GRID_PERSIST, NT, SMEM_TOTAL>>>(x, zidx, idxm, W1, b1, W2, b2,
                                             out, ntiles);
}

// round 11
// speedup vs baseline: 1.3396x; 1.3396x over previous
#include <cuda_runtime.h>
#include <cuda_bf16.h>
#include <cstdint>

// Problem constants (this instance): N=1e6 atoms, D=128, H=64, E=4, M=20000.
#define D_DIM 128
#define H_DIM 64
#define BM 64             // atoms per tile (2 CTAs/SM)
#define NT 256
#define E_MAX 8
#define PERM_CAP 1250000
#define HIST_BLOCKS 512
#define GRID_PERSIST 296  // 2 CTAs per SM

// dynamic SMEM layout (bytes), per CTA:
// A double buffered: buf s at s*32768 (AHI 16KB + ALO 16KB)
#define ABUF_STRIDE 32768
#define ALO_OFF 16384
#define OFF_BHI 65536
#define OFF_BLO 81920
#define OFF_SORIG 98304      // ring of 4 x 64 ints
#define OFF_B1ALL 99328
#define OFF_W2ALL 101376
#define OFF_ETAG  103424     // ring of 4 ints
#define SMEM_TOTAL 103936    // x2 CTAs = 207.9KB <= 228KB/SM

#define BWORDS 4096          // per-element W1 image: 4096 u32 (16KB)

__device__ int g_count[E_MAX];
__device__ int g_cursor[E_MAX];
__device__ int g_done;
__device__ int g_perm[PERM_CAP];
__device__ uint32_t g_Whi[E_MAX * BWORDS];
__device__ uint32_t g_Wlo[E_MAX * BWORDS];

// ---------------------------------------------------------------------------
__global__ void k_prep(float* __restrict__ out, const float* __restrict__ W1,
                       int E, int M, int total_slots) {
    int i = blockIdx.x * blockDim.x + threadIdx.x;
    int stride = gridDim.x * blockDim.x;
    for (int j = i; j < M; j += stride) out[j] = 0.0f;
    for (int j = i; j < total_slots; j += stride) g_perm[j] = -1;
    if (i < E_MAX) g_count[i] = 0;
    if (i == E_MAX) g_done = 0;

    for (int it = i; it < E * D_DIM * 16; it += stride) {
        int e = it >> 11;
        int k = (it >> 4) & 127;
        int n4 = it & 15;
        float4 v = *reinterpret_cast<const float4*>(
            W1 + (size_t)e * D_DIM * H_DIM + (size_t)k * H_DIM + n4 * 4);
        __nv_bfloat16 hx = __float2bfloat16(v.x), hy = __float2bfloat16(v.y);
        __nv_bfloat16 hz = __float2bfloat16(v.z), hw = __float2bfloat16(v.w);
        float rx = v.x - __bfloat162float(hx), ry = v.y - __bfloat162float(hy);
        float rz = v.z - __bfloat162float(hz), rw = v.w - __bfloat162float(hw);
        __nv_bfloat162 hi01 = __halves2bfloat162(hx, hy);
        __nv_bfloat162 hi23 = __halves2bfloat162(hz, hw);
        __nv_bfloat162 lo01 = __floats2bfloat162_rn(rx, ry);
        __nv_bfloat162 lo23 = __floats2bfloat162_rn(rz, rw);
        int w = e * BWORDS + k * 32 + (((n4 >> 1) ^ (k & 7)) << 2) + (n4 & 1) * 2;
        g_Whi[w]     = *reinterpret_cast<uint32_t*>(&hi01);
        g_Whi[w + 1] = *reinterpret_cast<uint32_t*>(&hi23);
        g_Wlo[w]     = *reinterpret_cast<uint32_t*>(&lo01);
        g_Wlo[w + 1] = *reinterpret_cast<uint32_t*>(&lo23);
    }
}

__global__ void k_histscan(const int* __restrict__ zidx, int n, int E) {
    __shared__ int sh[E_MAX];
    if (threadIdx.x < E_MAX) sh[threadIdx.x] = 0;
    __syncthreads();
    int i = blockIdx.x * blockDim.x + threadIdx.x;
    int stride = gridDim.x * blockDim.x;
    for (int j = i; j < n; j += stride) atomicAdd(&sh[zidx[j]], 1);
    __syncthreads();
    if (threadIdx.x < E) atomicAdd(&g_count[threadIdx.x], sh[threadIdx.x]);
    __threadfence();
    __syncthreads();
    if (threadIdx.x == 0) {
        int t = atomicAdd(&g_done, 1);
        if (t == gridDim.x - 1) {
            int off = 0;
            for (int e = 0; e < E; e++) {
                g_cursor[e] = off;
                off += ((g_count[e] + BM - 1) / BM) * BM;
            }
        }
    }
}

__global__ void k_scatter(const int* __restrict__ zidx, int n) {
    __shared__ int s_cnt[E_MAX];
    __shared__ int s_off[E_MAX];
    if (threadIdx.x < E_MAX) s_cnt[threadIdx.x] = 0;
    __syncthreads();
    int i = blockIdx.x * blockDim.x + threadIdx.x;
    int e = -1;
    if (i < n) { e = zidx[i]; atomicAdd(&s_cnt[e], 1); }
    __syncthreads();
    if (threadIdx.x < E_MAX && s_cnt[threadIdx.x] > 0)
        s_off[threadIdx.x] = atomicAdd(&g_cursor[threadIdx.x], s_cnt[threadIdx.x]);
    __syncthreads();
    if (threadIdx.x < E_MAX) s_cnt[threadIdx.x] = 0;
    __syncthreads();
    if (i < n) {
        int pos = s_off[e] + atomicAdd(&s_cnt[e], 1);
        g_perm[pos] = i;
    }
}

__device__ __forceinline__ float sspf(float v) {
    return __logf(fmaf(0.5f, __expf(v), 0.5f));
}
__device__ __forceinline__ void mma_bf16(float* c, const uint32_t* a,
                                         const uint32_t b0, const uint32_t b1) {
    asm volatile(
        "mma.sync.aligned.m16n8k16.row.col.f32.bf16.bf16.f32 "
        "{%0,%1,%2,%3}, {%4,%5,%6,%7}, {%8,%9}, {%0,%1,%2,%3};"
        : "+f"(c[0]), "+f"(c[1]), "+f"(c[2]), "+f"(c[3])
        : "r"(a[0]), "r"(a[1]), "r"(a[2]), "r"(a[3]), "r"(b0), "r"(b1));
}
__device__ __forceinline__ void ldsm_x4(uint32_t* r, uint32_t addr) {
    asm volatile("ldmatrix.sync.aligned.m8n8.x4.shared.b16 {%0,%1,%2,%3}, [%4];"
                 : "=r"(r[0]), "=r"(r[1]), "=r"(r[2]), "=r"(r[3]) : "r"(addr));
}
__device__ __forceinline__ void ldsm_x4t(uint32_t* r, uint32_t addr) {
    asm volatile("ldmatrix.sync.aligned.m8n8.x4.trans.shared.b16 {%0,%1,%2,%3}, [%4];"
                 : "=r"(r[0]), "=r"(r[1]), "=r"(r[2]), "=r"(r[3]) : "r"(addr));
}
__device__ __forceinline__ uint32_t smem_u32(const void* p) {
    return (uint32_t)__cvta_generic_to_shared(p);
}
__device__ __forceinline__ uint32_t cvt_bf16x2(float v1, float v0) {
    uint32_t r;
    asm("cvt.rn.bf16x2.f32 %0, %1, %2;" : "=r"(r) : "f"(v1), "f"(v0));
    return r;
}

__device__ __forceinline__ void store_a(char* abase, float4 v, int row, int lane) {
    uint32_t* AhiW = reinterpret_cast<uint32_t*>(abase);
    uint32_t* AloW = reinterpret_cast<uint32_t*>(abase + ALO_OFF);
    uint32_t xi0 = __float_as_uint(v.x), xi1 = __float_as_uint(v.y);
    uint32_t xi2 = __float_as_uint(v.z), xi3 = __float_as_uint(v.w);
    uint32_t h01 = __byte_perm(xi0, xi1, 0x7632);
    uint32_t h23 = __byte_perm(xi2, xi3, 0x7632);
    float l0 = v.x - __uint_as_float(xi0 & 0xffff0000u);
    float l1 = v.y - __uint_as_float(xi1 & 0xffff0000u);
    float l2 = v.z - __uint_as_float(xi2 & 0xffff0000u);
    float l3 = v.w - __uint_as_float(xi3 & 0xffff0000u);
    uint32_t l01 = cvt_bf16x2(l1, l0);
    uint32_t l23 = cvt_bf16x2(l3, l2);
    int w = row * 64 + ((((lane >> 1) ^ (row & 7)) << 2) + (lane & 1) * 2);
    *reinterpret_cast<uint2*>(&AhiW[w]) = make_uint2(h01, h23);
    *reinterpret_cast<uint2*>(&AloW[w]) = make_uint2(l01, l23);
}

__device__ __forceinline__ void stage_B(char* smem, int e, int tid) {
    const uint4* ghi = reinterpret_cast<const uint4*>(&g_Whi[e * BWORDS]);
    const uint4* glo = reinterpret_cast<const uint4*>(&g_Wlo[e * BWORDS]);
    uint4* shi = reinterpret_cast<uint4*>(smem + OFF_BHI);
    uint4* slo = reinterpret_cast<uint4*>(smem + OFF_BLO);
#pragma unroll
    for (int j = 0; j < 4; j++) {
        shi[j * NT + tid] = ghi[j * NT + tid];
        slo[j * NT + tid] = glo[j * NT + tid];
    }
}

// ---------------------------------------------------------------------------
// persistent main kernel (2 CTAs/SM): double-buffered A, single barrier per
// tile, depth-2 register prefetch, B re-staged only on element change.
// ---------------------------------------------------------------------------
__global__ __launch_bounds__(NT, 2)
void k_main(const float* __restrict__ x, const int* __restrict__ zidx,
            const int* __restrict__ idx_m,
            const float* __restrict__ W1, const float* __restrict__ b1,
            const float* __restrict__ W2, const float* __restrict__ b2,
            float* __restrict__ out, int ntiles) {
    extern __shared__ char smem[];
    int*   sOrig = reinterpret_cast<int*>(smem + OFF_SORIG);   // ring [4][64]
    float* b1all = reinterpret_cast<float*>(smem + OFF_B1ALL);
    float* w2all = reinterpret_cast<float*>(smem + OFF_W2ALL);
    int*   eTag  = reinterpret_cast<int*>(smem + OFF_ETAG);    // ring [4]

    int tid = threadIdx.x;
    int wid = tid >> 5;
    int lane = tid & 31;

    int q = (ntiles + gridDim.x - 1) / gridDim.x;
    int tstart = blockIdx.x * q;
    int tend = min(ntiles, tstart + q);
    if (tstart >= tend) return;
    int L = tend - tstart;

    for (int j = tid; j < E_MAX * H_DIM; j += NT) {
        b1all[j] = b1[j];
        w2all[j] = W2[j];
    }
    // sOrig ring slots 0..2, e-tags 0..2
    if (tid < BM) {
#pragma unroll
        for (int j = 0; j < 3; j++)
            sOrig[j * BM + tid] =
                (j < L) ? g_perm[(size_t)(tstart + j) * BM + tid] : -1;
    }
    if (tid < 3) {
        int o0 = (tid < L) ? g_perm[(size_t)(tstart + tid) * BM] : -1;
        eTag[tid] = (o0 >= 0) ? zidx[o0] : -1;
    }
    __syncthreads();

    int e_cur = eTag[0];
    if (e_cur < 0) return;
    stage_B(smem, e_cur, tid);

    // stage A(0) into buf0: 8 rows per pass (warp-per-row), 8 passes
#pragma unroll
    for (int it = 0; it < 8; it++) {
        int row = it * 8 + wid;
        int o = sOrig[row];
        float4 v = make_float4(0.f, 0.f, 0.f, 0.f);
        if (o >= 0)
            v = *reinterpret_cast<const float4*>(x + (size_t)o * D_DIM + lane * 4);
        store_a(smem, v, row, lane);
    }
    // prefetch x(1)
    float4 pref[8];
    if (L > 1) {
#pragma unroll
        for (int it = 0; it < 8; it++) {
            int row = it * 8 + wid;
            int o = sOrig[BM + row];
            pref[it] = make_float4(0.f, 0.f, 0.f, 0.f);
            if (o >= 0)
                pref[it] = *reinterpret_cast<const float4*>(
                    x + (size_t)o * D_DIM + lane * 4);
        }
    }
    __syncthreads();

    // fragment-lane decomposition (8 warps: 2 wm x 4 wn, warp tile 32x16)
    int wm = wid & 1;
    int wn = wid >> 1;
    int g = lane >> 2;
    int tg = lane & 3;
    int lane7 = lane & 7;
    int sub = lane >> 3;
    int subm = sub & 1;
    int subh = sub >> 1;

    uint32_t aBase0 = smem_u32(smem);
    uint32_t bHiBase = smem_u32(smem + OFF_BHI);
    uint32_t bLoBase = smem_u32(smem + OFF_BLO);

    int aRow0 = (wm * 32 + subm * 8 + lane7) * 64;
    int aRow1 = aRow0 + 16 * 64;
    int aXor = 4 * lane7;
    int a4h = 4 * subh;
    int bConst = (subm * 8 + lane7) * 32 + ((4 * (wn * 2 + subh)) ^ (4 * lane7));

    for (int l = 0; l < L; l++) {
        int s = l & 1;
        char* abase_nxt = smem + (s ^ 1) * ABUF_STRIDE;

        // 1. store A(l+1) from regs prefetched last iteration
        if (l + 1 < L) {
#pragma unroll
            for (int it = 0; it < 8; it++)
                store_a(abase_nxt, pref[it], it * 8 + wid, lane);
        }
        // 2. issue LDG for perm(l+3)
        int o3 = -1;
        if (tid < BM && l + 3 < L)
            o3 = g_perm[(size_t)(tstart + l + 3) * BM + tid];
        // 3. prefetch x(l+2) (latency hides under MMA)
        if (l + 2 < L) {
            const int* so = sOrig + ((l + 2) & 3) * BM;
#pragma unroll
            for (int it = 0; it < 8; it++) {
                int row = it * 8 + wid;
                int o = so[row];
                pref[it] = make_float4(0.f, 0.f, 0.f, 0.f);
                if (o >= 0)
                    pref[it] = *reinterpret_cast<const float4*>(
                        x + (size_t)o * D_DIM + lane * 4);
            }
        }

        // 4. MMA(l) on current buffer
        uint32_t aHiBase = aBase0 + s * ABUF_STRIDE;
        uint32_t aLoBase = aHiBase + ALO_OFF;
        float acc[2][2][4];
#pragma unroll
        for (int t2 = 0; t2 < 2; t2++)
#pragma unroll
            for (int u = 0; u < 2; u++)
#pragma unroll
                for (int qq = 0; qq < 4; qq++) acc[t2][u][qq] = 0.0f;

#pragma unroll
        for (int kb = 0; kb < 8; kb++) {
            int aOff = (8 * kb + a4h) ^ aXor;
            uint32_t ahi0[4], ahi1[4], alo0[4], alo1[4], bhi[4], blo[4];
            ldsm_x4(ahi0, aHiBase + (aRow0 + aOff) * 4);
            ldsm_x4(ahi1, aHiBase + (aRow1 + aOff) * 4);
            ldsm_x4(alo0, aLoBase + (aRow0 + aOff) * 4);
            ldsm_x4(alo1, aLoBase + (aRow1 + aOff) * 4);
            ldsm_x4t(bhi, bHiBase + (kb * 512 + bConst) * 4);
            ldsm_x4t(blo, bLoBase + (kb * 512 + bConst) * 4);
#pragma unroll
            for (int u = 0; u < 2; u++) {
                mma_bf16(acc[0][u], ahi0, bhi[2 * u], bhi[2 * u + 1]);
                mma_bf16(acc[0][u], ahi0, blo[2 * u], blo[2 * u + 1]);
                mma_bf16(acc[0][u], alo0, bhi[2 * u], bhi[2 * u + 1]);
                mma_bf16(acc[1][u], ahi1, bhi[2 * u], bhi[2 * u + 1]);
                mma_bf16(acc[1][u], ahi1, blo[2 * u], blo[2 * u + 1]);
                mma_bf16(acc[1][u], alo1, bhi[2 * u], bhi[2 * u + 1]);
            }
        }

        // 5. epilogue(l)
        {
            const int* so_t = sOrig + (l & 3) * BM;
            const float* b1s = b1all + e_cur * H_DIM;
            const float* w2s = w2all + e_cur * H_DIM;
            float b2e = b2[e_cur];
#pragma unroll
            for (int t2 = 0; t2 < 2; t2++) {
                float p0 = 0.0f, p1 = 0.0f;
#pragma unroll
                for (int u = 0; u < 2; u++) {
                    int c0 = wn * 16 + u * 8 + 2 * tg;
                    p0 = fmaf(sspf(acc[t2][u][0] + b1s[c0]),     w2s[c0],     p0);
                    p0 = fmaf(sspf(acc[t2][u][1] + b1s[c0 + 1]), w2s[c0 + 1], p0);
                    p1 = fmaf(sspf(acc[t2][u][2] + b1s[c0]),     w2s[c0],     p1);
                    p1 = fmaf(sspf(acc[t2][u][3] + b1s[c0 + 1]), w2s[c0 + 1], p1);
                }
                p0 += __shfl_xor_sync(0xffffffffu, p0, 1);
                p0 += __shfl_xor_sync(0xffffffffu, p0, 2);
                p1 += __shfl_xor_sync(0xffffffffu, p1, 1);
                p1 += __shfl_xor_sync(0xffffffffu, p1, 2);
                if (tg == 0) {
                    int r0 = wm * 32 + t2 * 16 + g;
                    int o0 = so_t[r0];
                    int o1 = so_t[r0 + 8];
                    float bias = (wn == 0) ? b2e : 0.0f;
                    if (o0 >= 0) atomicAdd(&out[idx_m[o0]], p0 + bias);
                    if (o1 >= 0) atomicAdd(&out[idx_m[o1]], p1 + bias);
                }
            }
        }

        // 6. commit perm(l+3) + element tag
        if (tid < BM) sOrig[((l + 3) & 3) * BM + tid] = o3;
        if (tid == 0) eTag[(l + 3) & 3] = (o3 >= 0) ? zidx[o3] : -1;

        // 7. single barrier
        __syncthreads();

        // 8. element change (rare): reload B with extra barrier
        if (l + 1 < L) {
            int e_next = eTag[(l + 1) & 3];
            if (e_next != e_cur && e_next >= 0) {
                stage_B(smem, e_next, tid);
                __syncthreads();
            }
            if (e_next >= 0) e_cur = e_next;
        }
    }
}

// ---------------------------------------------------------------------------
extern "C" void kernel_launch(void* const* d_in, const int* in_sizes, int n_in,
                              void* d_out, int out_size) {
    const float* x    = (const float*)d_in[0];
    const int*   zidx = (const int*)d_in[1];
    const int*   idxm = (const int*)d_in[2];
    const float* W1   = (const float*)d_in[3];
    const float* b1   = (const float*)d_in[4];
    const float* W2   = (const float*)d_in[5];
    const float* b2   = (const float*)d_in[6];
    float* out = (float*)d_out;

    int N = in_sizes[1];
    int E = in_sizes[6];
    int M = out_size;

    int ntiles = (N + BM - 1) / BM + E;
    int total_slots = ntiles * BM;
    if (total_slots > PERM_CAP) total_slots = PERM_CAP;

    static int smem_set = 0;
    if (!smem_set) {
        cudaFuncSetAttribute(k_main, cudaFuncAttributeMaxDynamicSharedMemorySize,
                             SMEM_TOTAL);
        smem_set = 1;
    }

    k_prep<<<256, 256>>>(out, W1, E, M, total_slots);
    k_histscan<<<HIST_BLOCKS, 256>>>(zidx, N, E);
    k_scatter<<<(N + 255) / 256, 256>>>(zidx, N);
    k_main<<<GRID_PERSIST, NT, SMEM_TOTAL>>>(x, zidx, idxm, W1, b1, W2, b2,
                                             out, ntiles);
}

// round 12
// speedup vs baseline: 1.4424x; 1.0767x over previous
#include <cuda_runtime.h>
#include <cuda_bf16.h>
#include <cstdint>

// Problem constants (this instance): N=1e6 atoms, D=128, H=64, E=4, M=20000.
#define D_DIM 128
#define H_DIM 64
#define BM 64             // atoms per tile
#define NT 256
#define E_MAX 8
#define PERM_CAP 1250000
#define HIST_BLOCKS 512
#define GRID_PERSIST 444  // 3 CTAs per SM

// dynamic SMEM layout (bytes), per CTA (single A buffer):
#define ALO_OFF   16384
#define OFF_BHI   32768
#define OFF_BLO   49152
#define OFF_SORIG 65536      // ring of 4 x 64 ints (1KB)
#define OFF_B1ALL 66560      // 2KB
#define OFF_W2ALL 68608      // 2KB
#define OFF_ETAG  70656      // ring of 4 ints
#define SMEM_TOTAL 70912     // x3 CTAs = 212.7KB <= 228KB/SM

#define BWORDS 4096          // per-element W1 image: 4096 u32 (16KB)

__device__ int g_count[E_MAX];
__device__ int g_cursor[E_MAX];
__device__ int g_done;
__device__ int g_perm[PERM_CAP];
__device__ uint32_t g_Whi[E_MAX * BWORDS];
__device__ uint32_t g_Wlo[E_MAX * BWORDS];

// ---------------------------------------------------------------------------
__global__ void k_prep(float* __restrict__ out, const float* __restrict__ W1,
                       int E, int M, int total_slots) {
    int i = blockIdx.x * blockDim.x + threadIdx.x;
    int stride = gridDim.x * blockDim.x;
    for (int j = i; j < M; j += stride) out[j] = 0.0f;
    for (int j = i; j < total_slots; j += stride) g_perm[j] = -1;
    if (i < E_MAX) g_count[i] = 0;
    if (i == E_MAX) g_done = 0;

    for (int it = i; it < E * D_DIM * 16; it += stride) {
        int e = it >> 11;
        int k = (it >> 4) & 127;
        int n4 = it & 15;
        float4 v = *reinterpret_cast<const float4*>(
            W1 + (size_t)e * D_DIM * H_DIM + (size_t)k * H_DIM + n4 * 4);
        __nv_bfloat16 hx = __float2bfloat16(v.x), hy = __float2bfloat16(v.y);
        __nv_bfloat16 hz = __float2bfloat16(v.z), hw = __float2bfloat16(v.w);
        float rx = v.x - __bfloat162float(hx), ry = v.y - __bfloat162float(hy);
        float rz = v.z - __bfloat162float(hz), rw = v.w - __bfloat162float(hw);
        __nv_bfloat162 hi01 = __halves2bfloat162(hx, hy);
        __nv_bfloat162 hi23 = __halves2bfloat162(hz, hw);
        __nv_bfloat162 lo01 = __floats2bfloat162_rn(rx, ry);
        __nv_bfloat162 lo23 = __floats2bfloat162_rn(rz, rw);
        int w = e * BWORDS + k * 32 + (((n4 >> 1) ^ (k & 7)) << 2) + (n4 & 1) * 2;
        g_Whi[w]     = *reinterpret_cast<uint32_t*>(&hi01);
        g_Whi[w + 1] = *reinterpret_cast<uint32_t*>(&hi23);
        g_Wlo[w]     = *reinterpret_cast<uint32_t*>(&lo01);
        g_Wlo[w + 1] = *reinterpret_cast<uint32_t*>(&lo23);
    }
}

__global__ void k_histscan(const int* __restrict__ zidx, int n, int E) {
    __shared__ int sh[E_MAX];
    if (threadIdx.x < E_MAX) sh[threadIdx.x] = 0;
    __syncthreads();
    int i = blockIdx.x * blockDim.x + threadIdx.x;
    int stride = gridDim.x * blockDim.x;
    for (int j = i; j < n; j += stride) atomicAdd(&sh[zidx[j]], 1);
    __syncthreads();
    if (threadIdx.x < E) atomicAdd(&g_count[threadIdx.x], sh[threadIdx.x]);
    __threadfence();
    __syncthreads();
    if (threadIdx.x == 0) {
        int t = atomicAdd(&g_done, 1);
        if (t == gridDim.x - 1) {
            int off = 0;
            for (int e = 0; e < E; e++) {
                g_cursor[e] = off;
                off += ((g_count[e] + BM - 1) / BM) * BM;
            }
        }
    }
}

__global__ void k_scatter(const int* __restrict__ zidx, int n) {
    __shared__ int s_cnt[E_MAX];
    __shared__ int s_off[E_MAX];
    if (threadIdx.x < E_MAX) s_cnt[threadIdx.x] = 0;
    __syncthreads();
    int i = blockIdx.x * blockDim.x + threadIdx.x;
    int e = -1;
    if (i < n) { e = zidx[i]; atomicAdd(&s_cnt[e], 1); }
    __syncthreads();
    if (threadIdx.x < E_MAX && s_cnt[threadIdx.x] > 0)
        s_off[threadIdx.x] = atomicAdd(&g_cursor[threadIdx.x], s_cnt[threadIdx.x]);
    __syncthreads();
    if (threadIdx.x < E_MAX) s_cnt[threadIdx.x] = 0;
    __syncthreads();
    if (i < n) {
        int pos = s_off[e] + atomicAdd(&s_cnt[e], 1);
        g_perm[pos] = i;
    }
}

__device__ __forceinline__ float sspf(float v) {
    return __logf(fmaf(0.5f, __expf(v), 0.5f));
}
__device__ __forceinline__ void mma_bf16(float* c, const uint32_t* a,
                                         const uint32_t b0, const uint32_t b1) {
    asm volatile(
        "mma.sync.aligned.m16n8k16.row.col.f32.bf16.bf16.f32 "
        "{%0,%1,%2,%3}, {%4,%5,%6,%7}, {%8,%9}, {%0,%1,%2,%3};"
        : "+f"(c[0]), "+f"(c[1]), "+f"(c[2]), "+f"(c[3])
        : "r"(a[0]), "r"(a[1]), "r"(a[2]), "r"(a[3]), "r"(b0), "r"(b1));
}
__device__ __forceinline__ void ldsm_x4(uint32_t* r, uint32_t addr) {
    asm volatile("ldmatrix.sync.aligned.m8n8.x4.shared.b16 {%0,%1,%2,%3}, [%4];"
                 : "=r"(r[0]), "=r"(r[1]), "=r"(r[2]), "=r"(r[3]) : "r"(addr));
}
__device__ __forceinline__ void ldsm_x4t(uint32_t* r, uint32_t addr) {
    asm volatile("ldmatrix.sync.aligned.m8n8.x4.trans.shared.b16 {%0,%1,%2,%3}, [%4];"
                 : "=r"(r[0]), "=r"(r[1]), "=r"(r[2]), "=r"(r[3]) : "r"(addr));
}
__device__ __forceinline__ uint32_t smem_u32(const void* p) {
    return (uint32_t)__cvta_generic_to_shared(p);
}
__device__ __forceinline__ uint32_t cvt_bf16x2(float v1, float v0) {
    uint32_t r;
    asm("cvt.rn.bf16x2.f32 %0, %1, %2;" : "=r"(r) : "f"(v1), "f"(v0));
    return r;
}

__device__ __forceinline__ void store_a(char* abase, float4 v, int row, int lane) {
    uint32_t* AhiW = reinterpret_cast<uint32_t*>(abase);
    uint32_t* AloW = reinterpret_cast<uint32_t*>(abase + ALO_OFF);
    uint32_t xi0 = __float_as_uint(v.x), xi1 = __float_as_uint(v.y);
    uint32_t xi2 = __float_as_uint(v.z), xi3 = __float_as_uint(v.w);
    uint32_t h01 = __byte_perm(xi0, xi1, 0x7632);
    uint32_t h23 = __byte_perm(xi2, xi3, 0x7632);
    float l0 = v.x - __uint_as_float(xi0 & 0xffff0000u);
    float l1 = v.y - __uint_as_float(xi1 & 0xffff0000u);
    float l2 = v.z - __uint_as_float(xi2 & 0xffff0000u);
    float l3 = v.w - __uint_as_float(xi3 & 0xffff0000u);
    uint32_t l01 = cvt_bf16x2(l1, l0);
    uint32_t l23 = cvt_bf16x2(l3, l2);
    int w = row * 64 + ((((lane >> 1) ^ (row & 7)) << 2) + (lane & 1) * 2);
    *reinterpret_cast<uint2*>(&AhiW[w]) = make_uint2(h01, h23);
    *reinterpret_cast<uint2*>(&AloW[w]) = make_uint2(l01, l23);
}

__device__ __forceinline__ void stage_B(char* smem, int e, int tid) {
    const uint4* ghi = reinterpret_cast<const uint4*>(&g_Whi[e * BWORDS]);
    const uint4* glo = reinterpret_cast<const uint4*>(&g_Wlo[e * BWORDS]);
    uint4* shi = reinterpret_cast<uint4*>(smem + OFF_BHI);
    uint4* slo = reinterpret_cast<uint4*>(smem + OFF_BLO);
#pragma unroll
    for (int j = 0; j < 4; j++) {
        shi[j * NT + tid] = ghi[j * NT + tid];
        slo[j * NT + tid] = glo[j * NT + tid];
    }
}

// ---------------------------------------------------------------------------
// persistent main kernel (3 CTAs/SM): single A buffer, two barriers/tile,
// half-register prefetch (rows 0-31) + JIT gather (rows 32-63); stalls
// covered by the two sibling CTAs.
// ---------------------------------------------------------------------------
__global__ __launch_bounds__(NT, 3)
void k_main(const float* __restrict__ x, const int* __restrict__ zidx,
            const int* __restrict__ idx_m,
            const float* __restrict__ W1, const float* __restrict__ b1,
            const float* __restrict__ W2, const float* __restrict__ b2,
            float* __restrict__ out, int ntiles) {
    extern __shared__ char smem[];
    int*   sOrig = reinterpret_cast<int*>(smem + OFF_SORIG);   // ring [4][64]
    float* b1all = reinterpret_cast<float*>(smem + OFF_B1ALL);
    float* w2all = reinterpret_cast<float*>(smem + OFF_W2ALL);
    int*   eTag  = reinterpret_cast<int*>(smem + OFF_ETAG);    // ring [4]

    int tid = threadIdx.x;
    int wid = tid >> 5;
    int lane = tid & 31;

    int q = (ntiles + gridDim.x - 1) / gridDim.x;
    int tstart = blockIdx.x * q;
    int tend = min(ntiles, tstart + q);
    if (tstart >= tend) return;
    int L = tend - tstart;

    for (int j = tid; j < E_MAX * H_DIM; j += NT) {
        b1all[j] = b1[j];
        w2all[j] = W2[j];
    }
    // sOrig ring slots 0,1 ; eTags 0,1
    if (tid < BM) {
#pragma unroll
        for (int j = 0; j < 2; j++)
            sOrig[j * BM + tid] =
                (j < L) ? g_perm[(size_t)(tstart + j) * BM + tid] : -1;
    }
    if (tid < 2) {
        int o0 = (tid < L) ? g_perm[(size_t)(tstart + tid) * BM] : -1;
        eTag[tid] = (o0 >= 0) ? zidx[o0] : -1;
    }
    __syncthreads();

    int e_cur = eTag[0];
    if (e_cur < 0) return;
    stage_B(smem, e_cur, tid);

    // prefetch x(0) rows 0-31 into regs (rows 32-63 gathered JIT in the loop)
    float4 pref[4];
#pragma unroll
    for (int it = 0; it < 4; it++) {
        int o = sOrig[it * 8 + wid];
        pref[it] = make_float4(0.f, 0.f, 0.f, 0.f);
        if (o >= 0)
            pref[it] = *reinterpret_cast<const float4*>(
                x + (size_t)o * D_DIM + lane * 4);
    }

    // fragment-lane decomposition (8 warps: 2 wm x 4 wn, warp tile 32x16)
    int wm = wid & 1;
    int wn = wid >> 1;
    int g = lane >> 2;
    int tg = lane & 3;
    int lane7 = lane & 7;
    int sub = lane >> 3;
    int subm = sub & 1;
    int subh = sub >> 1;

    uint32_t aHiBase = smem_u32(smem);
    uint32_t aLoBase = aHiBase + ALO_OFF;
    uint32_t bHiBase = smem_u32(smem + OFF_BHI);
    uint32_t bLoBase = smem_u32(smem + OFF_BLO);

    int aRow0 = (wm * 32 + subm * 8 + lane7) * 64;
    int aRow1 = aRow0 + 16 * 64;
    int aXor = 4 * lane7;
    int a4h = 4 * subh;
    int bConst = (subm * 8 + lane7) * 32 + ((4 * (wn * 2 + subh)) ^ (4 * lane7));

    for (int l = 0; l < L; l++) {
        const int* so = sOrig + (l & 3) * BM;

        // 1. STS A(l) rows 0-31 from pref (buffer free per barrier2 of l-1)
#pragma unroll
        for (int it = 0; it < 4; it++)
            store_a(smem, pref[it], it * 8 + wid, lane);

        // 2. JIT gather rows 32-63 (exposure covered by sibling CTAs)
        {
            float4 v[4];
#pragma unroll
            for (int it = 0; it < 4; it++) {
                int o = so[32 + it * 8 + wid];
                v[it] = make_float4(0.f, 0.f, 0.f, 0.f);
                if (o >= 0)
                    v[it] = *reinterpret_cast<const float4*>(
                        x + (size_t)o * D_DIM + lane * 4);
            }
#pragma unroll
            for (int it = 0; it < 4; it++)
                store_a(smem, v[it], 32 + it * 8 + wid, lane);
        }
        // 3. issue LDG for perm(l+2)
        int o2 = -1;
        if (tid < BM && l + 2 < L)
            o2 = g_perm[(size_t)(tstart + l + 2) * BM + tid];

        __syncthreads();   // barrier1: A (and B after change) visible

        // 4. prefetch x(l+1) rows 0-31 (LDG latency hides under MMA)
        if (l + 1 < L) {
            const int* sn = sOrig + ((l + 1) & 3) * BM;
#pragma unroll
            for (int it = 0; it < 4; it++) {
                int o = sn[it * 8 + wid];
                pref[it] = make_float4(0.f, 0.f, 0.f, 0.f);
                if (o >= 0)
                    pref[it] = *reinterpret_cast<const float4*>(
                        x + (size_t)o * D_DIM + lane * 4);
            }
        }

        // 5. MMA(l)
        float acc[2][2][4];
#pragma unroll
        for (int t2 = 0; t2 < 2; t2++)
#pragma unroll
            for (int u = 0; u < 2; u++)
#pragma unroll
                for (int qq = 0; qq < 4; qq++) acc[t2][u][qq] = 0.0f;

#pragma unroll
        for (int kb = 0; kb < 8; kb++) {
            int aOff = (8 * kb + a4h) ^ aXor;
            uint32_t ahi0[4], ahi1[4], alo0[4], alo1[4], bhi[4], blo[4];
            ldsm_x4(ahi0, aHiBase + (aRow0 + aOff) * 4);
            ldsm_x4(ahi1, aHiBase + (aRow1 + aOff) * 4);
            ldsm_x4(alo0, aLoBase + (aRow0 + aOff) * 4);
            ldsm_x4(alo1, aLoBase + (aRow1 + aOff) * 4);
            ldsm_x4t(bhi, bHiBase + (kb * 512 + bConst) * 4);
            ldsm_x4t(blo, bLoBase + (kb * 512 + bConst) * 4);
#pragma unroll
            for (int u = 0; u < 2; u++) {
                mma_bf16(acc[0][u], ahi0, bhi[2 * u], bhi[2 * u + 1]);
                mma_bf16(acc[0][u], ahi0, blo[2 * u], blo[2 * u + 1]);
                mma_bf16(acc[0][u], alo0, bhi[2 * u], bhi[2 * u + 1]);
                mma_bf16(acc[1][u], ahi1, bhi[2 * u], bhi[2 * u + 1]);
                mma_bf16(acc[1][u], ahi1, blo[2 * u], blo[2 * u + 1]);
                mma_bf16(acc[1][u], alo1, bhi[2 * u], bhi[2 * u + 1]);
            }
        }

        // 6. epilogue(l)
        {
            const float* b1s = b1all + e_cur * H_DIM;
            const float* w2s = w2all + e_cur * H_DIM;
            float b2e = b2[e_cur];
#pragma unroll
            for (int t2 = 0; t2 < 2; t2++) {
                float p0 = 0.0f, p1 = 0.0f;
#pragma unroll
                for (int u = 0; u < 2; u++) {
                    int c0 = wn * 16 + u * 8 + 2 * tg;
                    p0 = fmaf(sspf(acc[t2][u][0] + b1s[c0]),     w2s[c0],     p0);
                    p0 = fmaf(sspf(acc[t2][u][1] + b1s[c0 + 1]), w2s[c0 + 1], p0);
                    p1 = fmaf(sspf(acc[t2][u][2] + b1s[c0]),     w2s[c0],     p1);
                    p1 = fmaf(sspf(acc[t2][u][3] + b1s[c0 + 1]), w2s[c0 + 1], p1);
                }
                p0 += __shfl_xor_sync(0xffffffffu, p0, 1);
                p0 += __shfl_xor_sync(0xffffffffu, p0, 2);
                p1 += __shfl_xor_sync(0xffffffffu, p1, 1);
                p1 += __shfl_xor_sync(0xffffffffu, p1, 2);
                if (tg == 0) {
                    int r0 = wm * 32 + t2 * 16 + g;
                    int o0 = so[r0];
                    int o1 = so[r0 + 8];
                    float bias = (wn == 0) ? b2e : 0.0f;
                    if (o0 >= 0) atomicAdd(&out[idx_m[o0]], p0 + bias);
                    if (o1 >= 0) atomicAdd(&out[idx_m[o1]], p1 + bias);
                }
            }
        }

        // 7. commit perm(l+2) + element tag
        if (tid < BM) sOrig[((l + 2) & 3) * BM + tid] = o2;
        if (tid == 0) eTag[(l + 2) & 3] = (o2 >= 0) ? zidx[o2] : -1;

        __syncthreads();   // barrier2: MMA reads of A/B done, ring committed

        // 8. element change (rare): restage B (visible by next barrier1)
        if (l + 1 < L) {
            int e_next = eTag[(l + 1) & 3];
            if (e_next != e_cur && e_next >= 0) {
                stage_B(smem, e_next, tid);
            }
            if (e_next >= 0) e_cur = e_next;
        }
    }
}

// ---------------------------------------------------------------------------
extern "C" void kernel_launch(void* const* d_in, const int* in_sizes, int n_in,
                              void* d_out, int out_size) {
    const float* x    = (const float*)d_in[0];
    const int*   zidx = (const int*)d_in[1];
    const int*   idxm = (const int*)d_in[2];
    const float* W1   = (const float*)d_in[3];
    const float* b1   = (const float*)d_in[4];
    const float* W2   = (const float*)d_in[5];
    const float* b2   = (const float*)d_in[6];
    float* out = (float*)d_out;

    int N = in_sizes[1];
    int E = in_sizes[6];
    int M = out_size;

    int ntiles = (N + BM - 1) / BM + E;
    int total_slots = ntiles * BM;
    if (total_slots > PERM_CAP) total_slots = PERM_CAP;

    static int smem_set = 0;
    if (!smem_set) {
        cudaFuncSetAttribute(k_main, cudaFuncAttributeMaxDynamicSharedMemorySize,
                             SMEM_TOTAL);
        smem_set = 1;
    }

    k_prep<<<256, 256>>>(out, W1, E, M, total_slots);
    k_histscan<<<HIST_BLOCKS, 256>>>(zidx, N, E);
    k_scatter<<<(N + 255) / 256, 256>>>(zidx, N);
    k_main<<<GRID_PERSIST, NT, SMEM_TOTAL>>>(x, zidx, idxm, W1, b1, W2, b2,
                                             out, ntiles);
}

// round 13
// speedup vs baseline: 2.0906x; 1.4494x over previous
#include <cuda_runtime.h>
#include <cuda_fp16.h>
#include <cstdint>

// Problem constants (this instance): N=1e6 atoms, D=128, H=64, E=4, M=20000.
#define D_DIM 128
#define H_DIM 64
#define BM 64             // atoms per tile
#define NT 256
#define E_MAX 8
#define PERM_CAP 1250000
#define HIST_BLOCKS 512
#define GRID_PERSIST 592  // 4 CTAs per SM (occupancy cap: 32 warps)

// dynamic SMEM layout (bytes), per CTA (fp16 single-precision-term tiles):
#define OFF_A     0          // A: 64 rows x 128 k fp16 = 16KB
#define OFF_B     16384      // B: 128 k x 64 n fp16 = 16KB
#define OFF_SORIG 32768      // ring of 4 x 64 ints (1KB)
#define OFF_B1ALL 33792      // 2KB
#define OFF_W2ALL 35840      // 2KB
#define OFF_ETAG  37888      // ring of 4 ints
#define SMEM_TOTAL 38144     // x4 CTAs = 152.6KB <= 228KB/SM

#define BWORDS 4096          // per-element W1 fp16 image: 4096 u32 (16KB)

__device__ int g_count[E_MAX];
__device__ int g_cursor[E_MAX];
__device__ int g_done;
__device__ int g_perm[PERM_CAP];
__device__ uint32_t g_Wimg[E_MAX * BWORDS];

__device__ __forceinline__ uint32_t cvt_f16x2(float vhi, float vlo) {
    uint32_t r;   // r.lo = fp16(vlo), r.hi = fp16(vhi)
    asm("cvt.rn.f16x2.f32 %0, %1, %2;" : "=r"(r) : "f"(vhi), "f"(vlo));
    return r;
}

// ---------------------------------------------------------------------------
// prep: zero output/counters, fill perm with -1, pre-convert W1 into the
// swizzled fp16 tile image (once).
// ---------------------------------------------------------------------------
__global__ void k_prep(float* __restrict__ out, const float* __restrict__ W1,
                       int E, int M, int total_slots) {
    int i = blockIdx.x * blockDim.x + threadIdx.x;
    int stride = gridDim.x * blockDim.x;
    for (int j = i; j < M; j += stride) out[j] = 0.0f;
    for (int j = i; j < total_slots; j += stride) g_perm[j] = -1;
    if (i < E_MAX) g_count[i] = 0;
    if (i == E_MAX) g_done = 0;

    for (int it = i; it < E * D_DIM * 16; it += stride) {
        int e = it >> 11;
        int k = (it >> 4) & 127;
        int n4 = it & 15;
        float4 v = *reinterpret_cast<const float4*>(
            W1 + (size_t)e * D_DIM * H_DIM + (size_t)k * H_DIM + n4 * 4);
        uint32_t h01 = cvt_f16x2(v.y, v.x);
        uint32_t h23 = cvt_f16x2(v.w, v.z);
        int w = e * BWORDS + k * 32 + (((n4 >> 1) ^ (k & 7)) << 2) + (n4 & 1) * 2;
        g_Wimg[w]     = h01;
        g_Wimg[w + 1] = h23;
    }
}

__global__ void k_histscan(const int* __restrict__ zidx, int n, int E) {
    __shared__ int sh[E_MAX];
    if (threadIdx.x < E_MAX) sh[threadIdx.x] = 0;
    __syncthreads();
    int i = blockIdx.x * blockDim.x + threadIdx.x;
    int stride = gridDim.x * blockDim.x;
    for (int j = i; j < n; j += stride) atomicAdd(&sh[zidx[j]], 1);
    __syncthreads();
    if (threadIdx.x < E) atomicAdd(&g_count[threadIdx.x], sh[threadIdx.x]);
    __threadfence();
    __syncthreads();
    if (threadIdx.x == 0) {
        int t = atomicAdd(&g_done, 1);
        if (t == gridDim.x - 1) {
            int off = 0;
            for (int e = 0; e < E; e++) {
                g_cursor[e] = off;
                off += ((g_count[e] + BM - 1) / BM) * BM;
            }
        }
    }
}

__global__ void k_scatter(const int* __restrict__ zidx, int n) {
    __shared__ int s_cnt[E_MAX];
    __shared__ int s_off[E_MAX];
    if (threadIdx.x < E_MAX) s_cnt[threadIdx.x] = 0;
    __syncthreads();
    int i = blockIdx.x * blockDim.x + threadIdx.x;
    int e = -1;
    if (i < n) { e = zidx[i]; atomicAdd(&s_cnt[e], 1); }
    __syncthreads();
    if (threadIdx.x < E_MAX && s_cnt[threadIdx.x] > 0)
        s_off[threadIdx.x] = atomicAdd(&g_cursor[threadIdx.x], s_cnt[threadIdx.x]);
    __syncthreads();
    if (threadIdx.x < E_MAX) s_cnt[threadIdx.x] = 0;
    __syncthreads();
    if (i < n) {
        int pos = s_off[e] + atomicAdd(&s_cnt[e], 1);
        g_perm[pos] = i;
    }
}

__device__ __forceinline__ float sspf(float v) {
    return __logf(fmaf(0.5f, __expf(v), 0.5f));
}
__device__ __forceinline__ void mma_f16(float* c, const uint32_t* a,
                                        const uint32_t b0, const uint32_t b1) {
    asm volatile(
        "mma.sync.aligned.m16n8k16.row.col.f32.f16.f16.f32 "
        "{%0,%1,%2,%3}, {%4,%5,%6,%7}, {%8,%9}, {%0,%1,%2,%3};"
        : "+f"(c[0]), "+f"(c[1]), "+f"(c[2]), "+f"(c[3])
        : "r"(a[0]), "r"(a[1]), "r"(a[2]), "r"(a[3]), "r"(b0), "r"(b1));
}
__device__ __forceinline__ void ldsm_x4(uint32_t* r, uint32_t addr) {
    asm volatile("ldmatrix.sync.aligned.m8n8.x4.shared.b16 {%0,%1,%2,%3}, [%4];"
                 : "=r"(r[0]), "=r"(r[1]), "=r"(r[2]), "=r"(r[3]) : "r"(addr));
}
__device__ __forceinline__ void ldsm_x4t(uint32_t* r, uint32_t addr) {
    asm volatile("ldmatrix.sync.aligned.m8n8.x4.trans.shared.b16 {%0,%1,%2,%3}, [%4];"
                 : "=r"(r[0]), "=r"(r[1]), "=r"(r[2]), "=r"(r[3]) : "r"(addr));
}
__device__ __forceinline__ uint32_t smem_u32(const void* p) {
    return (uint32_t)__cvta_generic_to_shared(p);
}

// convert one float4 (4 k-values of one row) to fp16 and store swizzled
__device__ __forceinline__ void store_a(char* smem, float4 v, int row, int lane) {
    uint32_t* AW = reinterpret_cast<uint32_t*>(smem + OFF_A);
    uint32_t h01 = cvt_f16x2(v.y, v.x);
    uint32_t h23 = cvt_f16x2(v.w, v.z);
    int w = row * 64 + ((((lane >> 1) ^ (row & 7)) << 2) + (lane & 1) * 2);
    *reinterpret_cast<uint2*>(&AW[w]) = make_uint2(h01, h23);
}

__device__ __forceinline__ void stage_B(char* smem, int e, int tid) {
    const uint4* gw = reinterpret_cast<const uint4*>(&g_Wimg[e * BWORDS]);
    uint4* sw = reinterpret_cast<uint4*>(smem + OFF_B);
#pragma unroll
    for (int j = 0; j < 4; j++)
        sw[j * NT + tid] = gw[j * NT + tid];
}

// ---------------------------------------------------------------------------
// persistent main kernel (4 CTAs/SM): single fp16 MMA term, single A buffer,
// two barriers/tile, half-register prefetch + JIT gather; phase stalls
// covered by the three sibling CTAs.
// ---------------------------------------------------------------------------
__global__ __launch_bounds__(NT, 4)
void k_main(const float* __restrict__ x, const int* __restrict__ zidx,
            const int* __restrict__ idx_m,
            const float* __restrict__ W1, const float* __restrict__ b1,
            const float* __restrict__ W2, const float* __restrict__ b2,
            float* __restrict__ out, int ntiles) {
    extern __shared__ char smem[];
    int*   sOrig = reinterpret_cast<int*>(smem + OFF_SORIG);   // ring [4][64]
    float* b1all = reinterpret_cast<float*>(smem + OFF_B1ALL);
    float* w2all = reinterpret_cast<float*>(smem + OFF_W2ALL);
    int*   eTag  = reinterpret_cast<int*>(smem + OFF_ETAG);    // ring [4]

    int tid = threadIdx.x;
    int wid = tid >> 5;
    int lane = tid & 31;

    int q = (ntiles + gridDim.x - 1) / gridDim.x;
    int tstart = blockIdx.x * q;
    int tend = min(ntiles, tstart + q);
    if (tstart >= tend) return;
    int L = tend - tstart;

    for (int j = tid; j < E_MAX * H_DIM; j += NT) {
        b1all[j] = b1[j];
        w2all[j] = W2[j];
    }
    if (tid < BM) {
#pragma unroll
        for (int j = 0; j < 2; j++)
            sOrig[j * BM + tid] =
                (j < L) ? g_perm[(size_t)(tstart + j) * BM + tid] : -1;
    }
    if (tid < 2) {
        int o0 = (tid < L) ? g_perm[(size_t)(tstart + tid) * BM] : -1;
        eTag[tid] = (o0 >= 0) ? zidx[o0] : -1;
    }
    __syncthreads();

    int e_cur = eTag[0];
    if (e_cur < 0) return;
    stage_B(smem, e_cur, tid);

    // prefetch x(0) rows 0-31 (rows 32-63 gathered JIT in the loop)
    float4 pref[4];
#pragma unroll
    for (int it = 0; it < 4; it++) {
        int o = sOrig[it * 8 + wid];
        pref[it] = make_float4(0.f, 0.f, 0.f, 0.f);
        if (o >= 0)
            pref[it] = *reinterpret_cast<const float4*>(
                x + (size_t)o * D_DIM + lane * 4);
    }

    // fragment-lane decomposition (8 warps: 2 wm x 4 wn, warp tile 32x16)
    int wm = wid & 1;
    int wn = wid >> 1;
    int g = lane >> 2;
    int tg = lane & 3;
    int lane7 = lane & 7;
    int sub = lane >> 3;
    int subm = sub & 1;
    int subh = sub >> 1;

    uint32_t aBase = smem_u32(smem + OFF_A);
    uint32_t bBase = smem_u32(smem + OFF_B);

    int aRow0 = (wm * 32 + subm * 8 + lane7) * 64;
    int aRow1 = aRow0 + 16 * 64;
    int aXor = 4 * lane7;
    int a4h = 4 * subh;
    int bConst = (subm * 8 + lane7) * 32 + ((4 * (wn * 2 + subh)) ^ (4 * lane7));

    for (int l = 0; l < L; l++) {
        const int* so = sOrig + (l & 3) * BM;

        // 1. STS A(l) rows 0-31 from pref
#pragma unroll
        for (int it = 0; it < 4; it++)
            store_a(smem, pref[it], it * 8 + wid, lane);

        // 2. JIT gather rows 32-63 (exposure covered by sibling CTAs)
        {
            float4 v[4];
#pragma unroll
            for (int it = 0; it < 4; it++) {
                int o = so[32 + it * 8 + wid];
                v[it] = make_float4(0.f, 0.f, 0.f, 0.f);
                if (o >= 0)
                    v[it] = *reinterpret_cast<const float4*>(
                        x + (size_t)o * D_DIM + lane * 4);
            }
#pragma unroll
            for (int it = 0; it < 4; it++)
                store_a(smem, v[it], 32 + it * 8 + wid, lane);
        }
        // 3. issue LDG for perm(l+2)
        int o2 = -1;
        if (tid < BM && l + 2 < L)
            o2 = g_perm[(size_t)(tstart + l + 2) * BM + tid];

        __syncthreads();   // barrier1: A (and B after change) visible

        // 4. prefetch x(l+1) rows 0-31 (LDG latency hides under MMA)
        if (l + 1 < L) {
            const int* sn = sOrig + ((l + 1) & 3) * BM;
#pragma unroll
            for (int it = 0; it < 4; it++) {
                int o = sn[it * 8 + wid];
                pref[it] = make_float4(0.f, 0.f, 0.f, 0.f);
                if (o >= 0)
                    pref[it] = *reinterpret_cast<const float4*>(
                        x + (size_t)o * D_DIM + lane * 4);
            }
        }

        // 5. MMA(l): single fp16 term
        float acc[2][2][4];
#pragma unroll
        for (int t2 = 0; t2 < 2; t2++)
#pragma unroll
            for (int u = 0; u < 2; u++)
#pragma unroll
                for (int qq = 0; qq < 4; qq++) acc[t2][u][qq] = 0.0f;

#pragma unroll
        for (int kb = 0; kb < 8; kb++) {
            int aOff = (8 * kb + a4h) ^ aXor;
            uint32_t a0[4], a1[4], bb[4];
            ldsm_x4(a0, aBase + (aRow0 + aOff) * 4);
            ldsm_x4(a1, aBase + (aRow1 + aOff) * 4);
            ldsm_x4t(bb, bBase + (kb * 512 + bConst) * 4);
#pragma unroll
            for (int u = 0; u < 2; u++) {
                mma_f16(acc[0][u], a0, bb[2 * u], bb[2 * u + 1]);
                mma_f16(acc[1][u], a1, bb[2 * u], bb[2 * u + 1]);
            }
        }

        // 6. epilogue(l)
        {
            const float* b1s = b1all + e_cur * H_DIM;
            const float* w2s = w2all + e_cur * H_DIM;
            float b2e = b2[e_cur];
#pragma unroll
            for (int t2 = 0; t2 < 2; t2++) {
                float p0 = 0.0f, p1 = 0.0f;
#pragma unroll
                for (int u = 0; u < 2; u++) {
                    int c0 = wn * 16 + u * 8 + 2 * tg;
                    p0 = fmaf(sspf(acc[t2][u][0] + b1s[c0]),     w2s[c0],     p0);
                    p0 = fmaf(sspf(acc[t2][u][1] + b1s[c0 + 1]), w2s[c0 + 1], p0);
                    p1 = fmaf(sspf(acc[t2][u][2] + b1s[c0]),     w2s[c0],     p1);
                    p1 = fmaf(sspf(acc[t2][u][3] + b1s[c0 + 1]), w2s[c0 + 1], p1);
                }
                p0 += __shfl_xor_sync(0xffffffffu, p0, 1);
                p0 += __shfl_xor_sync(0xffffffffu, p0, 2);
                p1 += __shfl_xor_sync(0xffffffffu, p1, 1);
                p1 += __shfl_xor_sync(0xffffffffu, p1, 2);
                if (tg == 0) {
                    int r0 = wm * 32 + t2 * 16 + g;
                    int o0 = so[r0];
                    int o1 = so[r0 + 8];
                    float bias = (wn == 0) ? b2e : 0.0f;
                    if (o0 >= 0) atomicAdd(&out[idx_m[o0]], p0 + bias);
                    if (o1 >= 0) atomicAdd(&out[idx_m[o1]], p1 + bias);
                }
            }
        }

        // 7. commit perm(l+2) + element tag
        if (tid < BM) sOrig[((l + 2) & 3) * BM + tid] = o2;
        if (tid == 0) eTag[(l + 2) & 3] = (o2 >= 0) ? zidx[o2] : -1;

        __syncthreads();   // barrier2: MMA reads done, ring committed

        // 8. element change (rare): restage B (visible by next barrier1)
        if (l + 1 < L) {
            int e_next = eTag[(l + 1) & 3];
            if (e_next != e_cur && e_next >= 0) {
                stage_B(smem, e_next, tid);
            }
            if (e_next >= 0) e_cur = e_next;
        }
    }
}

// ---------------------------------------------------------------------------
extern "C" void kernel_launch(void* const* d_in, const int* in_sizes, int n_in,
                              void* d_out, int out_size) {
    const float* x    = (const float*)d_in[0];
    const int*   zidx = (const int*)d_in[1];
    const int*   idxm = (const int*)d_in[2];
    const float* W1   = (const float*)d_in[3];
    const float* b1   = (const float*)d_in[4];
    const float* W2   = (const float*)d_in[5];
    const float* b2   = (const float*)d_in[6];
    float* out = (float*)d_out;

    int N = in_sizes[1];
    int E = in_sizes[6];
    int M = out_size;

    int ntiles = (N + BM - 1) / BM + E;
    int total_slots = ntiles * BM;
    if (total_slots > PERM_CAP) total_slots = PERM_CAP;

    static int smem_set = 0;
    if (!smem_set) {
        cudaFuncSetAttribute(k_main, cudaFuncAttributeMaxDynamicSharedMemorySize,
                             SMEM_TOTAL);
        smem_set = 1;
    }

    k_prep<<<256, 256>>>(out, W1, E, M, total_slots);
    k_histscan<<<HIST_BLOCKS, 256>>>(zidx, N, E);
    k_scatter<<<(N + 255) / 256, 256>>>(zidx, N);
    k_main<<<GRID_PERSIST, NT, SMEM_TOTAL>>>(x, zidx, idxm, W1, b1, W2, b2,
                                             out, ntiles);
}